// round 1
// baseline (speedup 1.0000x reference)
#include <cuda_runtime.h>
#include <math.h>

#define BB 2
#define LL 192
#define DD 768
#define NCC 4
#define HH 256
#define KC 260            // H + NC
#define KPAD 264          // padded to multiple of 8

// Scratch for stage-1 projections (device globals: no allocation allowed)
__device__ float g_hp[BB*LL*HH];          // [b*L + l][H]
__device__ float g_ha[BB*LL*NCC*HH];      // [((b*L+l)*NC + n)*H + h]

// ---------------------------------------------------------------------------
// Stage 1: h_p = seq@Wp + bp ; h_a = seq@Wa + ba
// Combined GEMM: M=384 (B*L), K=768, N=1280 (256 for Wp, 1024 for Wa).
// 64x64 tile, 256 threads, 4x4 microtile.
// ---------------------------------------------------------------------------
__global__ __launch_bounds__(256) void proj_kernel(
    const float* __restrict__ seq,
    const float* __restrict__ Wp, const float* __restrict__ bp,
    const float* __restrict__ Wa, const float* __restrict__ ba)
{
    __shared__ float As[16][68];   // [k][m], padded
    __shared__ float Bs[16][68];   // [k][n], padded

    const int t  = threadIdx.x;
    const int tx = t & 15, ty = t >> 4;
    const int m0 = blockIdx.y * 64;
    const int n0 = blockIdx.x * 64;

    const float* Wsrc;
    int ldb, coff;
    if (n0 < HH) { Wsrc = Wp; ldb = HH;      coff = n0; }
    else         { Wsrc = Wa; ldb = NCC*HH;  coff = n0 - HH; }

    float acc[4][4];
    #pragma unroll
    for (int i = 0; i < 4; i++)
        #pragma unroll
        for (int j = 0; j < 4; j++) acc[i][j] = 0.f;

    for (int k0 = 0; k0 < DD; k0 += 16) {
        __syncthreads();
        // A tile: 64 rows x 16 k  (store transposed)
        {
            int k  = t & 15;
            int mb = t >> 4;
            #pragma unroll
            for (int e = 0; e < 4; e++) {
                int m = mb + e*16;
                As[k][m] = seq[(size_t)(m0 + m)*DD + k0 + k];
            }
        }
        // B tile: 16 k x 64 cols
        {
            int nc = t & 63;
            int kb = t >> 6;
            #pragma unroll
            for (int e = 0; e < 4; e++) {
                int k = kb + e*4;
                Bs[k][nc] = Wsrc[(size_t)(k0 + k)*ldb + coff + nc];
            }
        }
        __syncthreads();
        #pragma unroll
        for (int k = 0; k < 16; k++) {
            float4 a = *(const float4*)&As[k][ty*4];
            float4 b = *(const float4*)&Bs[k][tx*4];
            acc[0][0] += a.x*b.x; acc[0][1] += a.x*b.y; acc[0][2] += a.x*b.z; acc[0][3] += a.x*b.w;
            acc[1][0] += a.y*b.x; acc[1][1] += a.y*b.y; acc[1][2] += a.y*b.z; acc[1][3] += a.y*b.w;
            acc[2][0] += a.z*b.x; acc[2][1] += a.z*b.y; acc[2][2] += a.z*b.z; acc[2][3] += a.z*b.w;
            acc[3][0] += a.w*b.x; acc[3][1] += a.w*b.y; acc[3][2] += a.w*b.z; acc[3][3] += a.w*b.w;
        }
    }

    #pragma unroll
    for (int i = 0; i < 4; i++) {
        int m_g = m0 + ty*4 + i;
        #pragma unroll
        for (int e = 0; e < 4; e++) {
            int n_g = n0 + tx*4 + e;
            float v = acc[i][e];
            if (n_g < HH) {
                g_hp[(size_t)m_g*HH + n_g] = v + bp[n_g];
            } else {
                int c = n_g - HH;  // c = n*H + h
                g_ha[(size_t)m_g*NCC*HH + c] = v + ba[c];
            }
        }
    }
}

// ---------------------------------------------------------------------------
// Stage 2: fully fused refinement.
// Per block: one (b, n), tile of 8 p x 8 a = 64 tuples.
//   Ts[264][64]: A-matrix — rows 0..255 = tanh(h_p[p][c]+h_a[a][c]),
//                rows 256..259 = base_score[b,p,c-256,a], rows 260..263 = 0
//   K-loop over Wmid[n] (streamed via SMEM, reg-prefetched), 64x256 fp32 GEMM,
//   epilogue: out[b,p,n,a] = sum_h tanh(acc + bmid)*Wout (shfl-reduce over tx).
// ---------------------------------------------------------------------------
__device__ __forceinline__ void prefetchW(const float* __restrict__ Wn, int kt, int t,
                                          float4& w0, float4& w1)
{
    int k  = t >> 6;        // 0..3
    int c4 = t & 63;        // float4 column
    int c  = kt + k;
    w0 = make_float4(0.f, 0.f, 0.f, 0.f);
    w1 = make_float4(0.f, 0.f, 0.f, 0.f);
    if (c < KC)     w0 = *(const float4*)(Wn + (size_t)c*HH + c4*4);
    if (c + 4 < KC) w1 = *(const float4*)(Wn + (size_t)(c + 4)*HH + c4*4);
}

__global__ __launch_bounds__(256, 2) void fused_kernel(
    const float* __restrict__ base_score,  // [B,L,NC,L]
    const float* __restrict__ Wmid,        // [NC,260,256]
    const float* __restrict__ bmid,        // [NC,256]
    const float* __restrict__ Wout,        // [NC,256]
    float* __restrict__ out)               // [B,L,NC,L]
{
    extern __shared__ float sm[];
    float (*Ts)[64] = (float(*)[64])sm;       // KPAD x 64
    float* hp_s = sm + KPAD*64;               // 8 x 256
    float* ha_s = hp_s + 8*HH;                // 8 x 256
    float* Ws   = ha_s + 8*HH;                // 8 x 256

    const int t  = threadIdx.x;
    const int tx = t & 15, ty = t >> 4;
    const int bz = blockIdx.z;
    const int b  = bz >> 2, n = bz & 3;
    const int p0 = blockIdx.y * 8;
    const int a0 = blockIdx.x * 8;

    // Load h_p and h_a rows for this tile (8 x 256 each)
    #pragma unroll
    for (int e = 0; e < 8; e++) {
        int idx = t + e*256;
        int r = idx >> 8, c = idx & 255;
        hp_s[idx] = g_hp[(size_t)(b*LL + p0 + r)*HH + c];
        ha_s[idx] = g_ha[((size_t)(b*LL + a0 + r)*NCC + n)*HH + c];
    }
    __syncthreads();

    // Build Ts: tanh part (256 rows x 64 pairs = 64 per thread)
    #pragma unroll 4
    for (int idx = t; idx < HH*64; idx += 256) {
        int c = idx >> 6, pair = idx & 63;
        int p = pair >> 3, a = pair & 7;
        Ts[c][pair] = tanhf(hp_s[p*HH + c] + ha_s[a*HH + c]);
    }
    // bs rows (256..259) and zero pad (260..263): 2 entries per thread
    {
        int pair = t & 63, rr = t >> 6;   // rr 0..3
        int p = pair >> 3, a = pair & 7;
        Ts[HH + rr][pair] =
            base_score[((size_t)(b*LL + p0 + p)*NCC + rr)*LL + a0 + a];
        Ts[HH + 4 + rr][pair] = 0.f;
    }

    const float* Wn = Wmid + (size_t)n*KC*HH;
    float4 w0, w1;
    prefetchW(Wn, 0, t, w0, w1);

    float acc[4][16];
    #pragma unroll
    for (int i = 0; i < 4; i++)
        #pragma unroll
        for (int j = 0; j < 16; j++) acc[i][j] = 0.f;

    const int kTy = t >> 6;      // Ws store row
    const int c4  = t & 63;

    for (int kt = 0; kt < KPAD; kt += 8) {
        __syncthreads();   // previous compute done (and Ts ready on first iter)
        *(float4*)&Ws[kTy*HH + c4*4]       = w0;
        *(float4*)&Ws[(kTy + 4)*HH + c4*4] = w1;
        __syncthreads();   // Ws visible
        prefetchW(Wn, kt + 8, t, w0, w1);   // overlap next LDG with compute

        #pragma unroll
        for (int k = 0; k < 8; k++) {
            float4 av = *(const float4*)&Ts[kt + k][ty*4];
            #pragma unroll
            for (int j = 0; j < 4; j++) {
                float4 bv = *(const float4*)&Ws[k*HH + j*64 + tx*4];
                acc[0][j*4+0] += av.x*bv.x; acc[0][j*4+1] += av.x*bv.y;
                acc[0][j*4+2] += av.x*bv.z; acc[0][j*4+3] += av.x*bv.w;
                acc[1][j*4+0] += av.y*bv.x; acc[1][j*4+1] += av.y*bv.y;
                acc[1][j*4+2] += av.y*bv.z; acc[1][j*4+3] += av.y*bv.w;
                acc[2][j*4+0] += av.z*bv.x; acc[2][j*4+1] += av.z*bv.y;
                acc[2][j*4+2] += av.z*bv.z; acc[2][j*4+3] += av.z*bv.w;
                acc[3][j*4+0] += av.w*bv.x; acc[3][j*4+1] += av.w*bv.y;
                acc[3][j*4+2] += av.w*bv.z; acc[3][j*4+3] += av.w*bv.w;
            }
        }
    }

    // Epilogue: res[i] = sum_h tanh(acc + bmid[h]) * Wout[h]
    const float* bm = bmid + n*HH;
    const float* wo = Wout + n*HH;
    float res[4] = {0.f, 0.f, 0.f, 0.f};
    #pragma unroll
    for (int j = 0; j < 4; j++) {
        #pragma unroll
        for (int e = 0; e < 4; e++) {
            int hh  = j*64 + tx*4 + e;
            float bmv = __ldg(bm + hh);
            float wov = __ldg(wo + hh);
            #pragma unroll
            for (int i = 0; i < 4; i++)
                res[i] += tanhf(acc[i][j*4+e] + bmv) * wov;
        }
    }
    // reduce across the 16 tx lanes (same ty group is 16 consecutive lanes)
    #pragma unroll
    for (int off = 8; off > 0; off >>= 1) {
        #pragma unroll
        for (int i = 0; i < 4; i++)
            res[i] += __shfl_down_sync(0xffffffffu, res[i], off, 16);
    }
    if (tx == 0) {
        #pragma unroll
        for (int i = 0; i < 4; i++) {
            int m = ty*4 + i;
            int p = p0 + (m >> 3);
            int a = a0 + (m & 7);
            out[((size_t)(b*LL + p)*NCC + n)*LL + a] = res[i];
        }
    }
}

// ---------------------------------------------------------------------------
extern "C" void kernel_launch(void* const* d_in, const int* in_sizes, int n_in,
                              void* d_out, int out_size)
{
    const float* seq        = (const float*)d_in[0];
    const float* base_score = (const float*)d_in[1];
    const float* Wp         = (const float*)d_in[2];
    const float* bp         = (const float*)d_in[3];
    const float* Wa         = (const float*)d_in[4];
    const float* ba         = (const float*)d_in[5];
    const float* Wmid       = (const float*)d_in[6];
    const float* bmid       = (const float*)d_in[7];
    const float* Wout       = (const float*)d_in[8];
    float* out = (float*)d_out;

    proj_kernel<<<dim3(20, 6), 256>>>(seq, Wp, bp, Wa, ba);

    size_t smem = (size_t)(KPAD*64 + 3*8*HH) * sizeof(float);  // 92160 B
    cudaFuncSetAttribute(fused_kernel,
                         cudaFuncAttributeMaxDynamicSharedMemorySize, (int)smem);
    fused_kernel<<<dim3(LL/8, LL/8, BB*NCC), 256, smem>>>(
        base_score, Wmid, bmid, Wout, out);
}

// round 3
// speedup vs baseline: 2.9199x; 2.9199x over previous
#include <cuda_runtime.h>
#include <cuda_fp16.h>
#include <stdint.h>

#define BB 2
#define LL 192
#define DD 768
#define NCC 4
#define HH 256
#define KC 260            // real K (H + NC)
#define KCH 64            // k per chunk (fp16 row = 128 B)
#define NCH 5             // chunks (K padded to 320)

// ---------------- device scratch ----------------
__device__ float g_hp[BB * LL * HH];
__device__ float g_ha[BB * LL * NCC * HH];
// Pre-transposed, pre-swizzled fp16 Wmid images: [n][chunk][256 x 64 fp16 = 32KB]
__device__ unsigned char g_Wb[NCC * NCH * 32768];

// ---------------- helpers ----------------
__device__ __forceinline__ uint32_t smem_u32(const void* p) {
    uint32_t a;
    asm("{ .reg .u64 tmp; cvta.to.shared.u64 tmp, %1; cvt.u32.u64 %0, tmp; }"
        : "=r"(a) : "l"(p));
    return a;
}
__device__ __forceinline__ void ldsm4(uint32_t* r, uint32_t addr) {
    asm volatile("ldmatrix.sync.aligned.m8n8.x4.shared.b16 {%0,%1,%2,%3}, [%4];"
                 : "=r"(r[0]), "=r"(r[1]), "=r"(r[2]), "=r"(r[3]) : "r"(addr));
}
__device__ __forceinline__ void mma16816(float* d, const uint32_t* a, const uint32_t* b) {
    asm volatile("mma.sync.aligned.m16n8k16.row.col.f32.f16.f16.f32 "
                 "{%0,%1,%2,%3}, {%4,%5,%6,%7}, {%8,%9}, {%0,%1,%2,%3};"
                 : "+f"(d[0]), "+f"(d[1]), "+f"(d[2]), "+f"(d[3])
                 : "r"(a[0]), "r"(a[1]), "r"(a[2]), "r"(a[3]), "r"(b[0]), "r"(b[1]));
}
#define CP_ASYNC16(dst, src) \
    asm volatile("cp.async.cg.shared.global [%0], [%1], 16;" :: "r"(dst), "l"(src))
#define CP_COMMIT() asm volatile("cp.async.commit_group;" ::: "memory")
#define CP_WAIT1()  asm volatile("cp.async.wait_group 1;" ::: "memory")
#define CP_WAIT0()  asm volatile("cp.async.wait_group 0;" ::: "memory")

__device__ __forceinline__ float tanh_fast(float x) {
    float e = __expf(2.0f * x);              // MUFU.EX2 path
    return 1.0f - __fdividef(2.0f, e + 1.0f);
}
__device__ __forceinline__ uint32_t pack_h2(float v0, float v1) {
    __half2 h = __floats2half2_rn(v0, v1);
    return *reinterpret_cast<uint32_t*>(&h);
}
__device__ __forceinline__ uint32_t sw128(uint32_t byte) {
    return byte ^ ((byte >> 3) & 0x70);
}

// ---------------------------------------------------------------------------
// Stage 0: Wmid -> fp16 B images [h row][k col], 128B rows, SW128 swizzled.
// B[h][c_local] = Wmid[n][chunk*64 + c_local][h]; out-of-range K = 0.
// ---------------------------------------------------------------------------
__global__ __launch_bounds__(256) void prep_w(const float* __restrict__ Wmid) {
    int blk = blockIdx.x;                 // n*NCH + chunk
    int nn = blk / NCH, ch = blk % NCH;
    unsigned char* dst = g_Wb + (size_t)blk * 32768;
    int t = threadIdx.x;
    #pragma unroll
    for (int j = 0; j < 32; j++) {
        int idx = t + j * 256;            // 8192: h(256) x cpair(32)
        int hrow = idx >> 5, cp = idx & 31;
        int c = ch * KCH + cp * 2;
        float v0 = (c     < KC) ? Wmid[((size_t)nn * KC + c) * HH + hrow] : 0.0f;
        float v1 = (c + 1 < KC) ? Wmid[((size_t)nn * KC + c + 1) * HH + hrow] : 0.0f;
        *(uint32_t*)(dst + sw128((uint32_t)(hrow * 128 + cp * 4))) = pack_h2(v0, v1);
    }
}

// ---------------------------------------------------------------------------
// Stage 1: h_p = seq@Wp + bp ; h_a = seq@Wa + ba  (fp32, unchanged)
// ---------------------------------------------------------------------------
__global__ __launch_bounds__(256) void proj_kernel(
    const float* __restrict__ seq,
    const float* __restrict__ Wp, const float* __restrict__ bp,
    const float* __restrict__ Wa, const float* __restrict__ ba)
{
    __shared__ float As[16][68];
    __shared__ float Bs[16][68];

    const int t  = threadIdx.x;
    const int tx = t & 15, ty = t >> 4;
    const int m0 = blockIdx.y * 64;
    const int n0 = blockIdx.x * 64;

    const float* Wsrc;
    int ldb, coff;
    if (n0 < HH) { Wsrc = Wp; ldb = HH;       coff = n0; }
    else         { Wsrc = Wa; ldb = NCC * HH; coff = n0 - HH; }

    float acc[4][4];
    #pragma unroll
    for (int i = 0; i < 4; i++)
        #pragma unroll
        for (int j = 0; j < 4; j++) acc[i][j] = 0.f;

    for (int k0 = 0; k0 < DD; k0 += 16) {
        __syncthreads();
        {
            int k = t & 15, mb = t >> 4;
            #pragma unroll
            for (int e = 0; e < 4; e++) {
                int m = mb + e * 16;
                As[k][m] = seq[(size_t)(m0 + m) * DD + k0 + k];
            }
        }
        {
            int nc = t & 63, kb = t >> 6;
            #pragma unroll
            for (int e = 0; e < 4; e++) {
                int k = kb + e * 4;
                Bs[k][nc] = Wsrc[(size_t)(k0 + k) * ldb + coff + nc];
            }
        }
        __syncthreads();
        #pragma unroll
        for (int k = 0; k < 16; k++) {
            float4 a = *(const float4*)&As[k][ty * 4];
            float4 b = *(const float4*)&Bs[k][tx * 4];
            acc[0][0] += a.x*b.x; acc[0][1] += a.x*b.y; acc[0][2] += a.x*b.z; acc[0][3] += a.x*b.w;
            acc[1][0] += a.y*b.x; acc[1][1] += a.y*b.y; acc[1][2] += a.y*b.z; acc[1][3] += a.y*b.w;
            acc[2][0] += a.z*b.x; acc[2][1] += a.z*b.y; acc[2][2] += a.z*b.z; acc[2][3] += a.z*b.w;
            acc[3][0] += a.w*b.x; acc[3][1] += a.w*b.y; acc[3][2] += a.w*b.z; acc[3][3] += a.w*b.w;
        }
    }

    #pragma unroll
    for (int i = 0; i < 4; i++) {
        int m_g = m0 + ty * 4 + i;
        #pragma unroll
        for (int e = 0; e < 4; e++) {
            int n_g = n0 + tx * 4 + e;
            float v = acc[i][e];
            if (n_g < HH) g_hp[(size_t)m_g * HH + n_g] = v + bp[n_g];
            else {
                int c = n_g - HH;
                g_ha[(size_t)m_g * NCC * HH + c] = v + ba[c];
            }
        }
    }
}

// ---------------------------------------------------------------------------
// Stage 2: fused mma.sync fp16 GEMM + tanh epilogue.
// CTA = (b, n) x [16 p x 8 a] = 128 rows, N=256. 512 threads (16 warps, 4x4).
// ---------------------------------------------------------------------------
#define OFF_BM   0
#define OFF_WO   1024
#define OFF_RED  2048                     // 4 x 128 f32
#define OFF_HP   4096                     // 16 x 256 f32 = 16 KB
#define OFF_HA   20480                    // 8 x 256 f32  = 8 KB
#define OFF_BS   28672                    // 16 x 4 x 8 f32 = 2 KB
#define OFF_A    30720                    // 5 chunks x 16 KB (128 m x 128 B)
#define OFF_B    112640                   // 2 bufs x 32 KB
#define SMEM_TOTAL (OFF_B + 65536)        // 178176 B

__global__ __launch_bounds__(512, 1) void fused_mma(
    const float* __restrict__ base_score,   // [B,L,NC,L]
    const float* __restrict__ bmid,         // [NC,H]
    const float* __restrict__ Wout,         // [NC,H]
    float* __restrict__ out)                // [B,L,NC,L]
{
    extern __shared__ __align__(1024) char smem[];
    const uint32_t sb = smem_u32(smem);
    const int t = threadIdx.x;
    const int lane = t & 31, warp = t >> 5;
    const int wm = warp >> 2, wn = warp & 3;
    const int bz = blockIdx.z;
    const int b = bz >> 2, n = bz & 3;
    const int p0 = blockIdx.y * 16;
    const int a0 = blockIdx.x * 8;

    float* bm_s = (float*)(smem + OFF_BM);
    float* wo_s = (float*)(smem + OFF_WO);
    float* red  = (float*)(smem + OFF_RED);
    float* hp_s = (float*)(smem + OFF_HP);
    float* ha_s = (float*)(smem + OFF_HA);
    float* bs_s = (float*)(smem + OFF_BS);

    // Kick off B chunk 0 prefetch immediately (64 B per thread).
    {
        const char* src = (const char*)g_Wb + (size_t)(n * NCH) * 32768 + t * 64;
        uint32_t dst = sb + OFF_B + t * 64;
        CP_ASYNC16(dst, src); CP_ASYNC16(dst + 16, src + 16);
        CP_ASYNC16(dst + 32, src + 32); CP_ASYNC16(dst + 48, src + 48);
        CP_COMMIT();
    }

    // Prologue loads
    #pragma unroll
    for (int e = 0; e < 8; e++) {
        int idx = t + e * 512;                 // hp: 4096
        hp_s[idx] = g_hp[(size_t)(b * LL + p0 + (idx >> 8)) * HH + (idx & 255)];
    }
    #pragma unroll
    for (int e = 0; e < 4; e++) {
        int idx = t + e * 512;                 // ha: 2048
        ha_s[idx] = g_ha[((size_t)(b * LL + a0 + (idx >> 8)) * NCC + n) * HH + (idx & 255)];
    }
    {                                          // bs: 512 (p, cc, a)
        int p = t >> 5, cc = (t >> 3) & 3, a = t & 7;
        bs_s[t] = base_score[((size_t)(b * LL + p0 + p) * NCC + cc) * LL + a0 + a];
    }
    if (t < 256) { bm_s[t] = bmid[n * HH + t]; wo_s[t] = Wout[n * HH + t]; }
    __syncthreads();

    // Build A: all 5 chunks, fp16, SW128. 20480 pairs / 512 threads = 40 each.
    #pragma unroll 1
    for (int j = 0; j < 40; j++) {
        int idx = t + j * 512;
        int ch = idx >> 12, rem = idx & 4095;
        int m = rem >> 5, cp = rem & 31;
        int pm = m >> 3, am = m & 7;
        float v0, v1;
        if (ch < 4) {
            int c = ch * KCH + cp * 2;
            v0 = tanh_fast(hp_s[pm * HH + c]     + ha_s[am * HH + c]);
            v1 = tanh_fast(hp_s[pm * HH + c + 1] + ha_s[am * HH + c + 1]);
        } else {
            int kl = cp * 2;
            v0 = (kl     < 4) ? bs_s[pm * 32 + kl * 8 + am]       : 0.f;
            v1 = (kl + 1 < 4) ? bs_s[pm * 32 + (kl + 1) * 8 + am] : 0.f;
        }
        *(uint32_t*)(smem + OFF_A + ch * 16384 + sw128((uint32_t)(m * 128 + cp * 4)))
            = pack_h2(v0, v1);
    }

    // Per-lane ldmatrix address components
    const int mA   = wm * 32 + (lane & 15);
    const int kofA = (lane >> 4) * 16;
    const int nB   = wn * 64 + (lane & 7) + 8 * (lane >> 4);
    const int kofB = ((lane >> 3) & 1) * 16;

    float acc[2][8][4];
    #pragma unroll
    for (int mt = 0; mt < 2; mt++)
        #pragma unroll
        for (int nt = 0; nt < 8; nt++)
            #pragma unroll
            for (int e = 0; e < 4; e++) acc[mt][nt][e] = 0.f;

    #pragma unroll 1
    for (int ch = 0; ch < NCH; ch++) {
        const int buf = ch & 1;
        __syncthreads();                       // prior readers of buf^1 done; A ready (ch=0)
        if (ch + 1 < NCH) {
            const char* src = (const char*)g_Wb + (size_t)(n * NCH + ch + 1) * 32768 + t * 64;
            uint32_t dst = sb + OFF_B + (buf ^ 1) * 32768 + t * 64;
            CP_ASYNC16(dst, src); CP_ASYNC16(dst + 16, src + 16);
            CP_ASYNC16(dst + 32, src + 32); CP_ASYNC16(dst + 48, src + 48);
            CP_COMMIT();
            CP_WAIT1();
        } else {
            CP_WAIT0();
        }
        __syncthreads();                       // chunk ch visible to all

        const uint32_t abase = sb + OFF_A + ch * 16384;
        const uint32_t bbase = sb + OFF_B + buf * 32768;
        const int nks = (ch < 4) ? 4 : 1;      // chunk 4: only k rows 256..271

        for (int ks = 0; ks < nks; ks++) {
            uint32_t afr[2][4];
            #pragma unroll
            for (int mt = 0; mt < 2; mt++) {
                uint32_t byte = (uint32_t)((mA + mt * 16) * 128 + ks * 32 + kofA);
                ldsm4(afr[mt], abase + sw128(byte));
            }
            #pragma unroll
            for (int ntp = 0; ntp < 4; ntp++) {
                uint32_t bfr[4];
                uint32_t byte = (uint32_t)((nB + ntp * 16) * 128 + ks * 32 + kofB);
                ldsm4(bfr, bbase + sw128(byte));
                #pragma unroll
                for (int mt = 0; mt < 2; mt++) {
                    mma16816(acc[mt][2 * ntp],     afr[mt], bfr);
                    mma16816(acc[mt][2 * ntp + 1], afr[mt], bfr + 2);
                }
            }
        }
    }

    // Epilogue: tanh(acc + bmid)*Wout, reduce over h.
    float pr[2][2] = {{0.f, 0.f}, {0.f, 0.f}};
    #pragma unroll
    for (int mt = 0; mt < 2; mt++) {
        #pragma unroll
        for (int nt = 0; nt < 8; nt++) {
            int h0 = wn * 64 + nt * 8 + (lane & 3) * 2;
            float bm0 = bm_s[h0], bm1 = bm_s[h0 + 1];
            float w0 = wo_s[h0],  w1 = wo_s[h0 + 1];
            pr[mt][0] += tanh_fast(acc[mt][nt][0] + bm0) * w0
                       + tanh_fast(acc[mt][nt][1] + bm1) * w1;
            pr[mt][1] += tanh_fast(acc[mt][nt][2] + bm0) * w0
                       + tanh_fast(acc[mt][nt][3] + bm1) * w1;
        }
    }
    #pragma unroll
    for (int mt = 0; mt < 2; mt++)
        #pragma unroll
        for (int rh = 0; rh < 2; rh++) {
            float v = pr[mt][rh];
            v += __shfl_xor_sync(0xffffffffu, v, 1);
            v += __shfl_xor_sync(0xffffffffu, v, 2);
            if ((lane & 3) == 0)
                red[wn * 128 + wm * 32 + mt * 16 + rh * 8 + (lane >> 2)] = v;
        }
    __syncthreads();
    if (t < 128) {
        float r = red[t] + red[128 + t] + red[256 + t] + red[384 + t];
        int pm = t >> 3, am = t & 7;
        out[((size_t)(b * LL + p0 + pm) * NCC + n) * LL + a0 + am] = r;
    }
}

// ---------------------------------------------------------------------------
extern "C" void kernel_launch(void* const* d_in, const int* in_sizes, int n_in,
                              void* d_out, int out_size)
{
    const float* seq        = (const float*)d_in[0];
    const float* base_score = (const float*)d_in[1];
    const float* Wp         = (const float*)d_in[2];
    const float* bp         = (const float*)d_in[3];
    const float* Wa         = (const float*)d_in[4];
    const float* ba         = (const float*)d_in[5];
    const float* Wmid       = (const float*)d_in[6];
    const float* bmid       = (const float*)d_in[7];
    const float* Wout       = (const float*)d_in[8];
    float* out = (float*)d_out;

    prep_w<<<NCC * NCH, 256>>>(Wmid);
    proj_kernel<<<dim3(20, 6), 256>>>(seq, Wp, bp, Wa, ba);

    cudaFuncSetAttribute(fused_mma, cudaFuncAttributeMaxDynamicSharedMemorySize,
                         SMEM_TOTAL);
    fused_mma<<<dim3(LL / 8, LL / 16, BB * NCC), 512, SMEM_TOTAL>>>(
        base_score, bmid, Wout, out);
}